// round 13
// baseline (speedup 1.0000x reference)
#include <cuda_runtime.h>
#include <cuda_bf16.h>

// dRMSD, L=2048, B=8 — R13: single fused kernel, coalesced staged loads.
// A tile's 128 points are CONTIGUOUS 12KB spans of x / y in (L,B,3) layout:
// each block stages the span via coalesced float4 LDG into smem, transposes
// in-smem to bf16 hot-loop operands (R12's layout) — no prep kernel, no
// operand globals, no extra launch gap. bounds(128,8) targets 64 regs ->
// all 1088 blocks resident in one wave.

#define BATCH  8
#define NPTS   2047
#define NPAD   2048
#define TS     128
#define NT     (NPAD / TS)                 // 16
#define TPAIRS (NT * (NT + 1) / 2)         // 136
#define NBLK   (BATCH * TPAIRS)            // 1088
#define TPB    128
#define NF4    12288                       // total float4 per tensor (2048*8*3/4)

__device__ float    g_part[NBLK];
__device__ float    g_aux[BATCH][NT][9];
__device__ unsigned g_count;

__device__ __forceinline__ float sqrt_abs(float x) {
    float r; asm("sqrt.approx.f32 %0, %1;" : "=f"(r) : "f"(fabsf(x))); return r;
}
__device__ __forceinline__ __nv_bfloat162 u2b(unsigned u) {
    __nv_bfloat162 r; *reinterpret_cast<unsigned*>(&r) = u; return r;
}
__device__ __forceinline__ unsigned b2u(__nv_bfloat162 v) {
    return *reinterpret_cast<unsigned*>(&v);
}

__global__ __launch_bounds__(TPB, 8) void drmsd_kernel(
    const float* __restrict__ x, const float* __restrict__ y,
    float* __restrict__ out)
{
    int bid = blockIdx.x;
    int b = bid / TPAIRS;
    int t = bid - b * TPAIRS;
    int ti = (int)((33.0f - sqrtf((float)(1089 - 8 * t))) * 0.5f);
    if (ti * (33 - ti) / 2 > t) ti--;
    if ((ti + 1) * (33 - (ti + 1)) / 2 <= t) ti++;
    int tj = ti + (t - ti * (33 - ti) / 2);
    bool diag = (ti == tj);

    __shared__ __align__(16) float stage[3080];          // 12.3KB span window
    __shared__ __align__(16) __nv_bfloat16 sjh[8][TS];   // j operands (bf16)
    __shared__ __align__(16) float sif[8][TS];           // i coords+norms (fp32)
    int tid = threadIdx.x;

    // span of tile `tile`: rows tile*128+1 .. tile*128+128, batch b
    // float index F0 = 24*(tile*128+1) + 3b, length 3072
    int F0j = 24 * (tj * TS + 1) + 3 * b;
    int A0j = F0j & ~3;
    int offj = F0j - A0j;
    int F0i = 24 * (ti * TS + 1) + 3 * b;
    int A0i = F0i & ~3;
    int offi = F0i - A0i;

    #define LOAD_SPAN(SRC, A0)                                                \
    {                                                                         \
        int n4 = ((A0 & 3) + 3072 + 3) >> 2; /* == (off+3075)>>2, <=770 */    \
        n4 = (3072 + 3 + ((SRC##_off))) >> 2;                                 \
        (void)n4;                                                             \
    }
    #undef LOAD_SPAN

    // --- macro: coalesced float4 window load (guarded at tensor end) ---
    #define SPAN(SRCPTR, A0, OFF)                                             \
    {                                                                         \
        int n4_ = ((OFF) + 3072 + 3) >> 2;                                    \
        int g0_ = (A0) >> 2;                                                  \
        const float4* gp_ = reinterpret_cast<const float4*>(SRCPTR) + g0_;    \
        for (int k_ = tid; k_ < n4_; k_ += TPB) {                             \
            float4 v_ = (g0_ + k_ < NF4) ? gp_[k_]                            \
                                         : make_float4(0.f, 0.f, 0.f, 0.f);   \
            reinterpret_cast<float4*>(stage)[k_] = v_;                        \
        }                                                                     \
    }

    // ---- 1) x-span of j-tile -> sjh[0..3] (+ sif[0..3] if diag) ----
    SPAN(x, A0j, offj);
    __syncthreads();
    {
        int s = tj * TS + tid;
        float x0 = 0.f, x1 = 0.f, x2 = 0.f;
        if (s < NPTS) {
            int o = offj + tid * 24;
            x0 = stage[o]; x1 = stage[o + 1]; x2 = stage[o + 2];
        }
        float px = x0 * x0 + x1 * x1 + x2 * x2;
        sjh[0][tid] = __float2bfloat16(-2.f * x0);
        sjh[1][tid] = __float2bfloat16(-2.f * x1);
        sjh[2][tid] = __float2bfloat16(-2.f * x2);
        sjh[3][tid] = __float2bfloat16(px);
        if (diag) { sif[0][tid] = x0; sif[1][tid] = x1; sif[2][tid] = x2; sif[3][tid] = px; }
    }
    __syncthreads();

    // ---- 2) y-span of j-tile -> sjh[4..7] (+ sif[4..7] if diag) ----
    SPAN(y, A0j, offj);
    __syncthreads();
    {
        int s = tj * TS + tid;
        float y0 = 0.f, y1 = 0.f, y2 = 0.f;
        if (s < NPTS) {
            int o = offj + tid * 24;
            y0 = stage[o]; y1 = stage[o + 1]; y2 = stage[o + 2];
        }
        float py = y0 * y0 + y1 * y1 + y2 * y2;
        sjh[4][tid] = __float2bfloat16(-2.f * y0);
        sjh[5][tid] = __float2bfloat16(-2.f * y1);
        sjh[6][tid] = __float2bfloat16(-2.f * y2);
        sjh[7][tid] = __float2bfloat16(py);
        if (diag) { sif[4][tid] = y0; sif[5][tid] = y1; sif[6][tid] = y2; sif[7][tid] = py; }
    }

    // ---- 3) i-tile spans (off-diagonal only) -> sif fp32 ----
    if (!diag) {
        __syncthreads();
        SPAN(x, A0i, offi);
        __syncthreads();
        {
            int s = ti * TS + tid;
            float x0 = 0.f, x1 = 0.f, x2 = 0.f;
            if (s < NPTS) {
                int o = offi + tid * 24;
                x0 = stage[o]; x1 = stage[o + 1]; x2 = stage[o + 2];
            }
            sif[0][tid] = x0; sif[1][tid] = x1; sif[2][tid] = x2;
            sif[3][tid] = x0 * x0 + x1 * x1 + x2 * x2;
        }
        __syncthreads();
        SPAN(y, A0i, offi);
        __syncthreads();
        {
            int s = ti * TS + tid;
            float y0 = 0.f, y1 = 0.f, y2 = 0.f;
            if (s < NPTS) {
                int o = offi + tid * 24;
                y0 = stage[o]; y1 = stage[o + 1]; y2 = stage[o + 2];
            }
            sif[4][tid] = y0; sif[5][tid] = y1; sif[6][tid] = y2;
            sif[7][tid] = y0 * y0 + y1 * y1 + y2 * y2;
        }
    }
    __syncthreads();
    #undef SPAN

    // ---- per-tile moments (diagonal blocks only; exact fp32) ----
    if (diag) {
        float ipx = sif[3][tid], ipy = sif[7][tid];
        float v[9] = { ipx, sif[0][tid], sif[1][tid], sif[2][tid],
                       ipy, sif[4][tid], sif[5][tid], sif[6][tid],
                       sqrtf(ipx * ipy) };
        #pragma unroll
        for (int off = 16; off > 0; off >>= 1)
            #pragma unroll
            for (int q = 0; q < 9; q++)
                v[q] += __shfl_down_sync(0xffffffffu, v[q], off);
        __shared__ float waux[TPB / 32][9];
        if ((tid & 31) == 0)
            #pragma unroll
            for (int q = 0; q < 9; q++) waux[tid >> 5][q] = v[q];
        __syncthreads();
        if (tid == 0)
            #pragma unroll
            for (int q = 0; q < 9; q++)
                g_aux[b][ti][q] = waux[0][q] + waux[1][q] + waux[2][q] + waux[3][q];
    }

    // ---- hot loop: 2 i per lane, warp-split j halves, bf16x2 (R10/R12) ----
    int w = tid >> 5, lane = tid & 31;
    int jbase = (w & 1) * 64;
    int i0 = (w >> 1) * 64 + lane;
    int i1 = i0 + 32;

    __nv_bfloat162 X00 = __float2bfloat162_rn(sif[0][i0]);
    __nv_bfloat162 X01 = __float2bfloat162_rn(sif[1][i0]);
    __nv_bfloat162 X02 = __float2bfloat162_rn(sif[2][i0]);
    __nv_bfloat162 PX0 = __float2bfloat162_rn(sif[3][i0]);
    __nv_bfloat162 Y00 = __float2bfloat162_rn(sif[4][i0]);
    __nv_bfloat162 Y01 = __float2bfloat162_rn(sif[5][i0]);
    __nv_bfloat162 Y02 = __float2bfloat162_rn(sif[6][i0]);
    __nv_bfloat162 PY0 = __float2bfloat162_rn(sif[7][i0]);
    __nv_bfloat162 X10 = __float2bfloat162_rn(sif[0][i1]);
    __nv_bfloat162 X11 = __float2bfloat162_rn(sif[1][i1]);
    __nv_bfloat162 X12 = __float2bfloat162_rn(sif[2][i1]);
    __nv_bfloat162 PX1 = __float2bfloat162_rn(sif[3][i1]);
    __nv_bfloat162 Y10 = __float2bfloat162_rn(sif[4][i1]);
    __nv_bfloat162 Y11 = __float2bfloat162_rn(sif[5][i1]);
    __nv_bfloat162 Y12 = __float2bfloat162_rn(sif[6][i1]);
    __nv_bfloat162 PY1 = __float2bfloat162_rn(sif[7][i1]);

    float a00 = 0.f, a01 = 0.f, a10 = 0.f, a11 = 0.f;

    #define GROUP(CW0, CW1, CW2, CWN, DW0, DW1, DW2, DWN, XX0, XX1, XX2, PPX, YY0, YY1, YY2, PPY, S0, S1) { \
        __nv_bfloat162 tx_ = __hfma2(u2b(CW0), XX0, __hfma2(u2b(CW1), XX1,      \
                              __hfma2(u2b(CW2), XX2, __hadd2(u2b(CWN), PPX)))); \
        __nv_bfloat162 ty_ = __hfma2(u2b(DW0), YY0, __hfma2(u2b(DW1), YY1,      \
                              __hfma2(u2b(DW2), YY2, __hadd2(u2b(DWN), PPY)))); \
        unsigned pv_ = b2u(__hmul2(tx_, ty_));                                  \
        S0 += sqrt_abs(__uint_as_float(pv_ << 16));                             \
        S1 += sqrt_abs(__uint_as_float(pv_ & 0xffff0000u));                     \
    }

    #pragma unroll 2
    for (int jc = 0; jc < 8; jc++) {
        int jo = jbase + jc * 8;
        uint4 c0 = *reinterpret_cast<const uint4*>(&sjh[0][jo]);
        uint4 c1 = *reinterpret_cast<const uint4*>(&sjh[1][jo]);
        uint4 c2 = *reinterpret_cast<const uint4*>(&sjh[2][jo]);
        uint4 cn = *reinterpret_cast<const uint4*>(&sjh[3][jo]);
        uint4 d0 = *reinterpret_cast<const uint4*>(&sjh[4][jo]);
        uint4 d1 = *reinterpret_cast<const uint4*>(&sjh[5][jo]);
        uint4 d2 = *reinterpret_cast<const uint4*>(&sjh[6][jo]);
        uint4 dn = *reinterpret_cast<const uint4*>(&sjh[7][jo]);

        GROUP(c0.x, c1.x, c2.x, cn.x, d0.x, d1.x, d2.x, dn.x,
              X00, X01, X02, PX0, Y00, Y01, Y02, PY0, a00, a01)
        GROUP(c0.x, c1.x, c2.x, cn.x, d0.x, d1.x, d2.x, dn.x,
              X10, X11, X12, PX1, Y10, Y11, Y12, PY1, a10, a11)
        GROUP(c0.y, c1.y, c2.y, cn.y, d0.y, d1.y, d2.y, dn.y,
              X00, X01, X02, PX0, Y00, Y01, Y02, PY0, a00, a01)
        GROUP(c0.y, c1.y, c2.y, cn.y, d0.y, d1.y, d2.y, dn.y,
              X10, X11, X12, PX1, Y10, Y11, Y12, PY1, a10, a11)
        GROUP(c0.z, c1.z, c2.z, cn.z, d0.z, d1.z, d2.z, dn.z,
              X00, X01, X02, PX0, Y00, Y01, Y02, PY0, a00, a01)
        GROUP(c0.z, c1.z, c2.z, cn.z, d0.z, d1.z, d2.z, dn.z,
              X10, X11, X12, PX1, Y10, Y11, Y12, PY1, a10, a11)
        GROUP(c0.w, c1.w, c2.w, cn.w, d0.w, d1.w, d2.w, dn.w,
              X00, X01, X02, PX0, Y00, Y01, Y02, PY0, a00, a01)
        GROUP(c0.w, c1.w, c2.w, cn.w, d0.w, d1.w, d2.w, dn.w,
              X10, X11, X12, PX1, Y10, Y11, Y12, PY1, a10, a11)
    }
    #undef GROUP

    float val = (a00 + a01) + (a10 + a11);

    // deterministic block reduce
    #pragma unroll
    for (int off = 16; off > 0; off >>= 1)
        val += __shfl_down_sync(0xffffffffu, val, off);
    __shared__ float wsum[TPB / 32];
    if ((tid & 31) == 0) wsum[tid >> 5] = val;
    __syncthreads();
    if (tid == 0) {
        float s = wsum[0] + wsum[1] + wsum[2] + wsum[3];
        g_part[bid] = diag ? s : 2.0f * s;
    }

    // ---- last-block final reduction ----
    __shared__ bool isLast;
    if (tid == 0) {
        __threadfence();
        unsigned v = atomicAdd(&g_count, 1u);
        isLast = (v == (unsigned)(gridDim.x - 1));
    }
    __syncthreads();
    if (!isLast) return;
    __threadfence();

    int b2 = tid >> 4;
    int l  = tid & 15;

    float wacc = 0.f;
    for (int k = l; k < TPAIRS; k += 16)
        wacc += g_part[b2 * TPAIRS + k];
    float a[9];
    #pragma unroll
    for (int q = 0; q < 9; q++) a[q] = g_aux[b2][l][q];

    #pragma unroll
    for (int off = 8; off > 0; off >>= 1) {
        wacc += __shfl_down_sync(0xffffffffu, wacc, off, 16);
        #pragma unroll
        for (int q = 0; q < 9; q++)
            a[q] += __shfl_down_sync(0xffffffffu, a[q], off, 16);
    }

    __shared__ float norms[BATCH];
    if (l == 0) {
        float n = (float)NPTS;
        float T = 2.0f * (n * a[0] - (a[1] * a[1] + a[2] * a[2] + a[3] * a[3]))
                + 2.0f * (n * a[4] - (a[5] * a[5] + a[6] * a[6] + a[7] * a[7]));
        float W = wacc - 2.0f * a[8];
        float S = T - 2.0f * W;
        if (S < 0.f) S = 0.f;
        norms[b2] = sqrtf(S);
    }
    __syncthreads();
    if (tid == 0) {
        float tot = 0.f;
        #pragma unroll
        for (int i = 0; i < BATCH; i++) tot += norms[i];
        float n = (float)NPTS;
        out[0] = tot / sqrtf(n * n - n) / (float)BATCH;
        g_count = 0;
    }
}

extern "C" void kernel_launch(void* const* d_in, const int* in_sizes, int n_in,
                              void* d_out, int out_size) {
    const float* x = (const float*)d_in[0];
    const float* y = (const float*)d_in[1];
    (void)in_sizes; (void)n_in; (void)out_size;
    drmsd_kernel<<<NBLK, TPB>>>(x, y, (float*)d_out);
}

// round 14
// speedup vs baseline: 1.1098x; 1.1098x over previous
#include <cuda_runtime.h>
#include <cuda_bf16.h>

// dRMSD, L=2048, B=8.
// R14 = R12 two-kernel packaging, single-wave main kernel:
//  - prep (32 blocks): coalesced transpose -> g_jb (SoA bf16 j-operands)
//    and g_ia (AoS bf16 i-operands: [b][s][8]).
//  - main: j-tile = 1 LDG.128/thread; i-splats = 2 LDG.128 + PRMT dups;
//    bounds(128,8) -> 61-64 regs -> 8 blocks/SM -> all 1088 blocks in ONE wave
//    (R12 ran 74 regs = 6/SM = 2 waves, ~18% tail).
//  - hot loop identical to R10/R12 (bf16x2 Gram, 2 i/lane, warp-split j).

#define BATCH  8
#define NPTS   2047
#define NPAD   2048
#define TS     128
#define NT     (NPAD / TS)                 // 16
#define TPAIRS (NT * (NT + 1) / 2)         // 136
#define NBLK   (BATCH * TPAIRS)            // 1088
#define TPB    128

__device__ __align__(16) __nv_bfloat16 g_jb[BATCH][8][NPAD]; // -2x(3),|x|^2,-2y(3),|y|^2
__device__ __align__(16) __nv_bfloat16 g_ia[BATCH][NPAD][8]; // x(3),|x|^2,y(3),|y|^2 (AoS)
__device__ float    g_part[NBLK];
__device__ float    g_aux[BATCH][NT][9];
__device__ unsigned g_count;

__device__ __forceinline__ float sqrt_abs(float x) {
    float r; asm("sqrt.approx.f32 %0, %1;" : "=f"(r) : "f"(fabsf(x))); return r;
}
__device__ __forceinline__ __nv_bfloat162 u2b(unsigned u) {
    __nv_bfloat162 r; *reinterpret_cast<unsigned*>(&r) = u; return r;
}
__device__ __forceinline__ unsigned b2u(__nv_bfloat162 v) {
    return *reinterpret_cast<unsigned*>(&v);
}
__device__ __forceinline__ unsigned bf16_of(float f) {   // rn convert, return bits
    __nv_bfloat16 h = __float2bfloat16(f);
    return (unsigned)*reinterpret_cast<unsigned short*>(&h);
}

// ---------------- prep: coalesced transpose + operand precompute ------------
#define PREP_T 384
__global__ __launch_bounds__(PREP_T) void prep_kernel(
    const float* __restrict__ x, const float* __restrict__ y)
{
    __shared__ float sx[1536], sy[1536];   // 64 rows x 8 batches x 3 coords
    int r0 = blockIdx.x * 64;              // 32 blocks cover 2048 rows
    int tid = threadIdx.x;

    reinterpret_cast<float4*>(sx)[tid] =
        reinterpret_cast<const float4*>(x + r0 * 24)[tid];
    reinterpret_cast<float4*>(sy)[tid] =
        reinterpret_cast<const float4*>(y + r0 * 24)[tid];
    __syncthreads();

    for (int p = tid; p < 512; p += PREP_T) {   // 64 rows x 8 batches
        int b  = p >> 6;
        int rl = p & 63;
        int row = r0 + rl;
        if (row < 1) continue;                  // row 0 dropped by the mask
        int s = row - 1;                        // gathered index 0..2046
        int o = (rl * 8 + b) * 3;
        float x0 = sx[o], x1 = sx[o + 1], x2 = sx[o + 2];
        float y0 = sy[o], y1 = sy[o + 1], y2 = sy[o + 2];
        float px = x0 * x0 + x1 * x1 + x2 * x2;
        float py = y0 * y0 + y1 * y1 + y2 * y2;
        // j-operands (SoA)
        g_jb[b][0][s] = __float2bfloat16(-2.f * x0);
        g_jb[b][1][s] = __float2bfloat16(-2.f * x1);
        g_jb[b][2][s] = __float2bfloat16(-2.f * x2);
        g_jb[b][3][s] = __float2bfloat16(px);
        g_jb[b][4][s] = __float2bfloat16(-2.f * y0);
        g_jb[b][5][s] = __float2bfloat16(-2.f * y1);
        g_jb[b][6][s] = __float2bfloat16(-2.f * y2);
        g_jb[b][7][s] = __float2bfloat16(py);
        // i-operands (AoS, one 16B store)
        uint4 pack;
        pack.x = bf16_of(x0) | (bf16_of(x1) << 16);
        pack.y = bf16_of(x2) | (bf16_of(px) << 16);
        pack.z = bf16_of(y0) | (bf16_of(y1) << 16);
        pack.w = bf16_of(y2) | (bf16_of(py) << 16);
        *reinterpret_cast<uint4*>(&g_ia[b][s][0]) = pack;
    }
}

// ---------------- main ------------------------------------------------------
__global__ __launch_bounds__(TPB, 8) void drmsd_kernel(
    const float* __restrict__ x, const float* __restrict__ y,
    float* __restrict__ out)
{
    int bid = blockIdx.x;
    int b = bid / TPAIRS;
    int t = bid - b * TPAIRS;
    int ti = (int)((33.0f - sqrtf((float)(1089 - 8 * t))) * 0.5f);
    if (ti * (33 - ti) / 2 > t) ti--;
    if ((ti + 1) * (33 - (ti + 1)) / 2 <= t) ti++;
    int tj = ti + (t - ti * (33 - ti) / 2);
    bool diag = (ti == tj);

    __shared__ __align__(16) __nv_bfloat16 sjh[8][TS];
    int tid = threadIdx.x;

    // ---- j-tile: one coalesced LDG.128 + STS.128 per thread ----
    {
        int ch  = tid >> 4;
        int t16 = tid & 15;
        const uint4* src = reinterpret_cast<const uint4*>(&g_jb[b][ch][tj * TS]);
        reinterpret_cast<uint4*>(&sjh[ch][0])[t16] = src[t16];
    }

    // ---- per-tile moments (diagonal blocks only; exact fp32 path) ----
    if (diag) {
        float ix0 = 0.f, ix1 = 0.f, ix2 = 0.f, iy0 = 0.f, iy1 = 0.f, iy2 = 0.f;
        int s = ti * TS + tid;
        if (s < NPTS) {
            int base = ((s + 1) * BATCH + b) * 3;
            ix0 = x[base]; ix1 = x[base + 1]; ix2 = x[base + 2];
            iy0 = y[base]; iy1 = y[base + 1]; iy2 = y[base + 2];
        }
        float ipx = ix0 * ix0 + ix1 * ix1 + ix2 * ix2;
        float ipy = iy0 * iy0 + iy1 * iy1 + iy2 * iy2;
        float v[9] = { ipx, ix0, ix1, ix2, ipy, iy0, iy1, iy2, sqrtf(ipx * ipy) };
        #pragma unroll
        for (int off = 16; off > 0; off >>= 1)
            #pragma unroll
            for (int q = 0; q < 9; q++)
                v[q] += __shfl_down_sync(0xffffffffu, v[q], off);
        __shared__ float waux[TPB / 32][9];
        if ((tid & 31) == 0)
            #pragma unroll
            for (int q = 0; q < 9; q++) waux[tid >> 5][q] = v[q];
        __syncthreads();
        if (tid == 0)
            #pragma unroll
            for (int q = 0; q < 9; q++)
                g_aux[b][ti][q] = waux[0][q] + waux[1][q] + waux[2][q] + waux[3][q];
    }

    // ---- i-splats: 2 LDG.128 (AoS) + PRMT dups ----
    int w = tid >> 5, lane = tid & 31;
    int jbase = (w & 1) * 64;
    int s0 = ti * TS + (w >> 1) * 64 + lane;
    int s1 = s0 + 32;

    uint4 ia = *reinterpret_cast<const uint4*>(&g_ia[b][s0][0]);
    uint4 ib = *reinterpret_cast<const uint4*>(&g_ia[b][s1][0]);

    __nv_bfloat162 X00 = u2b(__byte_perm(ia.x, ia.x, 0x1010));
    __nv_bfloat162 X01 = u2b(__byte_perm(ia.x, ia.x, 0x3232));
    __nv_bfloat162 X02 = u2b(__byte_perm(ia.y, ia.y, 0x1010));
    __nv_bfloat162 PX0 = u2b(__byte_perm(ia.y, ia.y, 0x3232));
    __nv_bfloat162 Y00 = u2b(__byte_perm(ia.z, ia.z, 0x1010));
    __nv_bfloat162 Y01 = u2b(__byte_perm(ia.z, ia.z, 0x3232));
    __nv_bfloat162 Y02 = u2b(__byte_perm(ia.w, ia.w, 0x1010));
    __nv_bfloat162 PY0 = u2b(__byte_perm(ia.w, ia.w, 0x3232));
    __nv_bfloat162 X10 = u2b(__byte_perm(ib.x, ib.x, 0x1010));
    __nv_bfloat162 X11 = u2b(__byte_perm(ib.x, ib.x, 0x3232));
    __nv_bfloat162 X12 = u2b(__byte_perm(ib.y, ib.y, 0x1010));
    __nv_bfloat162 PX1 = u2b(__byte_perm(ib.y, ib.y, 0x3232));
    __nv_bfloat162 Y10 = u2b(__byte_perm(ib.z, ib.z, 0x1010));
    __nv_bfloat162 Y11 = u2b(__byte_perm(ib.z, ib.z, 0x3232));
    __nv_bfloat162 Y12 = u2b(__byte_perm(ib.w, ib.w, 0x1010));
    __nv_bfloat162 PY1 = u2b(__byte_perm(ib.w, ib.w, 0x3232));

    __syncthreads();   // sjh ready

    float a00 = 0.f, a01 = 0.f, a10 = 0.f, a11 = 0.f;

    #define GROUP(CW0, CW1, CW2, CWN, DW0, DW1, DW2, DWN, XX0, XX1, XX2, PPX, YY0, YY1, YY2, PPY, S0, S1) { \
        __nv_bfloat162 tx_ = __hfma2(u2b(CW0), XX0, __hfma2(u2b(CW1), XX1,      \
                              __hfma2(u2b(CW2), XX2, __hadd2(u2b(CWN), PPX)))); \
        __nv_bfloat162 ty_ = __hfma2(u2b(DW0), YY0, __hfma2(u2b(DW1), YY1,      \
                              __hfma2(u2b(DW2), YY2, __hadd2(u2b(DWN), PPY)))); \
        unsigned pv_ = b2u(__hmul2(tx_, ty_));                                  \
        S0 += sqrt_abs(__uint_as_float(pv_ << 16));                             \
        S1 += sqrt_abs(__uint_as_float(pv_ & 0xffff0000u));                     \
    }

    #pragma unroll 2
    for (int jc = 0; jc < 8; jc++) {
        int jo = jbase + jc * 8;
        uint4 c0 = *reinterpret_cast<const uint4*>(&sjh[0][jo]);
        uint4 c1 = *reinterpret_cast<const uint4*>(&sjh[1][jo]);
        uint4 c2 = *reinterpret_cast<const uint4*>(&sjh[2][jo]);
        uint4 cn = *reinterpret_cast<const uint4*>(&sjh[3][jo]);
        uint4 d0 = *reinterpret_cast<const uint4*>(&sjh[4][jo]);
        uint4 d1 = *reinterpret_cast<const uint4*>(&sjh[5][jo]);
        uint4 d2 = *reinterpret_cast<const uint4*>(&sjh[6][jo]);
        uint4 dn = *reinterpret_cast<const uint4*>(&sjh[7][jo]);

        GROUP(c0.x, c1.x, c2.x, cn.x, d0.x, d1.x, d2.x, dn.x,
              X00, X01, X02, PX0, Y00, Y01, Y02, PY0, a00, a01)
        GROUP(c0.x, c1.x, c2.x, cn.x, d0.x, d1.x, d2.x, dn.x,
              X10, X11, X12, PX1, Y10, Y11, Y12, PY1, a10, a11)
        GROUP(c0.y, c1.y, c2.y, cn.y, d0.y, d1.y, d2.y, dn.y,
              X00, X01, X02, PX0, Y00, Y01, Y02, PY0, a00, a01)
        GROUP(c0.y, c1.y, c2.y, cn.y, d0.y, d1.y, d2.y, dn.y,
              X10, X11, X12, PX1, Y10, Y11, Y12, PY1, a10, a11)
        GROUP(c0.z, c1.z, c2.z, cn.z, d0.z, d1.z, d2.z, dn.z,
              X00, X01, X02, PX0, Y00, Y01, Y02, PY0, a00, a01)
        GROUP(c0.z, c1.z, c2.z, cn.z, d0.z, d1.z, d2.z, dn.z,
              X10, X11, X12, PX1, Y10, Y11, Y12, PY1, a10, a11)
        GROUP(c0.w, c1.w, c2.w, cn.w, d0.w, d1.w, d2.w, dn.w,
              X00, X01, X02, PX0, Y00, Y01, Y02, PY0, a00, a01)
        GROUP(c0.w, c1.w, c2.w, cn.w, d0.w, d1.w, d2.w, dn.w,
              X10, X11, X12, PX1, Y10, Y11, Y12, PY1, a10, a11)
    }
    #undef GROUP

    float val = (a00 + a01) + (a10 + a11);

    // deterministic block reduce
    #pragma unroll
    for (int off = 16; off > 0; off >>= 1)
        val += __shfl_down_sync(0xffffffffu, val, off);
    __shared__ float wsum[TPB / 32];
    if ((tid & 31) == 0) wsum[tid >> 5] = val;
    __syncthreads();
    if (tid == 0) {
        float s = wsum[0] + wsum[1] + wsum[2] + wsum[3];
        g_part[bid] = diag ? s : 2.0f * s;
    }

    // ---- last-block final reduction ----
    __shared__ bool isLast;
    if (tid == 0) {
        __threadfence();
        unsigned v = atomicAdd(&g_count, 1u);
        isLast = (v == (unsigned)(gridDim.x - 1));
    }
    __syncthreads();
    if (!isLast) return;
    __threadfence();

    int b2 = tid >> 4;
    int l  = tid & 15;

    float wacc = 0.f;
    for (int k = l; k < TPAIRS; k += 16)
        wacc += g_part[b2 * TPAIRS + k];
    float a[9];
    #pragma unroll
    for (int q = 0; q < 9; q++) a[q] = g_aux[b2][l][q];

    #pragma unroll
    for (int off = 8; off > 0; off >>= 1) {
        wacc += __shfl_down_sync(0xffffffffu, wacc, off, 16);
        #pragma unroll
        for (int q = 0; q < 9; q++)
            a[q] += __shfl_down_sync(0xffffffffu, a[q], off, 16);
    }

    __shared__ float norms[BATCH];
    if (l == 0) {
        float n = (float)NPTS;
        float T = 2.0f * (n * a[0] - (a[1] * a[1] + a[2] * a[2] + a[3] * a[3]))
                + 2.0f * (n * a[4] - (a[5] * a[5] + a[6] * a[6] + a[7] * a[7]));
        float W = wacc - 2.0f * a[8];
        float S = T - 2.0f * W;
        if (S < 0.f) S = 0.f;
        norms[b2] = sqrtf(S);
    }
    __syncthreads();
    if (tid == 0) {
        float tot = 0.f;
        #pragma unroll
        for (int i = 0; i < BATCH; i++) tot += norms[i];
        float n = (float)NPTS;
        out[0] = tot / sqrtf(n * n - n) / (float)BATCH;
        g_count = 0;
    }
}

extern "C" void kernel_launch(void* const* d_in, const int* in_sizes, int n_in,
                              void* d_out, int out_size) {
    const float* x = (const float*)d_in[0];
    const float* y = (const float*)d_in[1];
    (void)in_sizes; (void)n_in; (void)out_size;
    prep_kernel<<<32, PREP_T>>>(x, y);
    drmsd_kernel<<<NBLK, TPB>>>(x, y, (float*)d_out);
}

// round 15
// speedup vs baseline: 1.2277x; 1.1062x over previous
#include <cuda_runtime.h>
#include <cuda_bf16.h>

// dRMSD, L=2048, B=8.
// R15 = R14 prep/packaging + 4x bigger tiles: TS=256, TPB=256, 288 blocks.
// Same pair count, but per-block prologue/reduction overhead pool shrinks
// ~3.8x and tile loads amortize over 4x the pairs. bounds(256,2): only 2
// resident blocks/SM needed (288/148), so ptxas gets full reg freedom.
// Hot loop byte-identical bf16x2 Gram GROUP (R10/R12/R14).

#define BATCH  8
#define NPTS   2047
#define NPAD   2048
#define TS     256
#define NT     (NPAD / TS)                 // 8
#define TPAIRS (NT * (NT + 1) / 2)         // 36
#define NBLK   (BATCH * TPAIRS)            // 288
#define TPB    256

__device__ __align__(16) __nv_bfloat16 g_jb[BATCH][8][NPAD]; // -2x(3),|x|^2,-2y(3),|y|^2
__device__ __align__(16) __nv_bfloat16 g_ia[BATCH][NPAD][8]; // x(3),|x|^2,y(3),|y|^2 (AoS)
__device__ float    g_part[NBLK];
__device__ float    g_aux[BATCH][NT][9];
__device__ unsigned g_count;

__device__ __forceinline__ float sqrt_abs(float x) {
    float r; asm("sqrt.approx.f32 %0, %1;" : "=f"(r) : "f"(fabsf(x))); return r;
}
__device__ __forceinline__ __nv_bfloat162 u2b(unsigned u) {
    __nv_bfloat162 r; *reinterpret_cast<unsigned*>(&r) = u; return r;
}
__device__ __forceinline__ unsigned b2u(__nv_bfloat162 v) {
    return *reinterpret_cast<unsigned*>(&v);
}
__device__ __forceinline__ unsigned bf16_of(float f) {
    __nv_bfloat16 h = __float2bfloat16(f);
    return (unsigned)*reinterpret_cast<unsigned short*>(&h);
}

// ---------------- prep: coalesced transpose + operand precompute ------------
#define PREP_T 384
__global__ __launch_bounds__(PREP_T) void prep_kernel(
    const float* __restrict__ x, const float* __restrict__ y)
{
    __shared__ float sx[1536], sy[1536];   // 64 rows x 8 batches x 3 coords
    int r0 = blockIdx.x * 64;              // 32 blocks cover 2048 rows
    int tid = threadIdx.x;

    reinterpret_cast<float4*>(sx)[tid] =
        reinterpret_cast<const float4*>(x + r0 * 24)[tid];
    reinterpret_cast<float4*>(sy)[tid] =
        reinterpret_cast<const float4*>(y + r0 * 24)[tid];
    __syncthreads();

    for (int p = tid; p < 512; p += PREP_T) {   // 64 rows x 8 batches
        int b  = p >> 6;
        int rl = p & 63;
        int row = r0 + rl;
        if (row < 1) continue;                  // row 0 dropped by the mask
        int s = row - 1;                        // gathered index 0..2046
        int o = (rl * 8 + b) * 3;
        float x0 = sx[o], x1 = sx[o + 1], x2 = sx[o + 2];
        float y0 = sy[o], y1 = sy[o + 1], y2 = sy[o + 2];
        float px = x0 * x0 + x1 * x1 + x2 * x2;
        float py = y0 * y0 + y1 * y1 + y2 * y2;
        g_jb[b][0][s] = __float2bfloat16(-2.f * x0);
        g_jb[b][1][s] = __float2bfloat16(-2.f * x1);
        g_jb[b][2][s] = __float2bfloat16(-2.f * x2);
        g_jb[b][3][s] = __float2bfloat16(px);
        g_jb[b][4][s] = __float2bfloat16(-2.f * y0);
        g_jb[b][5][s] = __float2bfloat16(-2.f * y1);
        g_jb[b][6][s] = __float2bfloat16(-2.f * y2);
        g_jb[b][7][s] = __float2bfloat16(py);
        uint4 pack;
        pack.x = bf16_of(x0) | (bf16_of(x1) << 16);
        pack.y = bf16_of(x2) | (bf16_of(px) << 16);
        pack.z = bf16_of(y0) | (bf16_of(y1) << 16);
        pack.w = bf16_of(y2) | (bf16_of(py) << 16);
        *reinterpret_cast<uint4*>(&g_ia[b][s][0]) = pack;
    }
}

// ---------------- main ------------------------------------------------------
__global__ __launch_bounds__(TPB, 2) void drmsd_kernel(
    const float* __restrict__ x, const float* __restrict__ y,
    float* __restrict__ out)
{
    int bid = blockIdx.x;
    int b = bid / TPAIRS;
    int t = bid - b * TPAIRS;
    // triangular decode, NT=8: first index of row k = k*(17-k)/2; 289-8S=(17-2k)^2
    int ti = (int)((17.0f - sqrtf((float)(289 - 8 * t))) * 0.5f);
    if (ti * (17 - ti) / 2 > t) ti--;
    if ((ti + 1) * (16 - ti) / 2 <= t) ti++;
    int tj = ti + (t - ti * (17 - ti) / 2);
    bool diag = (ti == tj);

    __shared__ __align__(16) __nv_bfloat16 sjh[8][TS];
    int tid = threadIdx.x;

    // ---- j-tile: one coalesced LDG.128 + STS.128 per thread ----
    {
        int ch  = tid >> 5;                // 0..7 channels
        int t32 = tid & 31;                // 32 x 16B = 512B per channel
        const uint4* src = reinterpret_cast<const uint4*>(&g_jb[b][ch][tj * TS]);
        reinterpret_cast<uint4*>(&sjh[ch][0])[t32] = src[t32];
    }

    // ---- per-tile moments (diagonal blocks only; exact fp32 path) ----
    if (diag) {
        float ix0 = 0.f, ix1 = 0.f, ix2 = 0.f, iy0 = 0.f, iy1 = 0.f, iy2 = 0.f;
        int s = ti * TS + tid;
        if (s < NPTS) {
            int base = ((s + 1) * BATCH + b) * 3;
            ix0 = x[base]; ix1 = x[base + 1]; ix2 = x[base + 2];
            iy0 = y[base]; iy1 = y[base + 1]; iy2 = y[base + 2];
        }
        float ipx = ix0 * ix0 + ix1 * ix1 + ix2 * ix2;
        float ipy = iy0 * iy0 + iy1 * iy1 + iy2 * iy2;
        float v[9] = { ipx, ix0, ix1, ix2, ipy, iy0, iy1, iy2, sqrtf(ipx * ipy) };
        #pragma unroll
        for (int off = 16; off > 0; off >>= 1)
            #pragma unroll
            for (int q = 0; q < 9; q++)
                v[q] += __shfl_down_sync(0xffffffffu, v[q], off);
        __shared__ float waux[TPB / 32][9];
        if ((tid & 31) == 0)
            #pragma unroll
            for (int q = 0; q < 9; q++) waux[tid >> 5][q] = v[q];
        __syncthreads();
        if (tid == 0) {
            #pragma unroll
            for (int q = 0; q < 9; q++) {
                float s9 = 0.f;
                #pragma unroll
                for (int ww = 0; ww < TPB / 32; ww++) s9 += waux[ww][q];
                g_aux[b][ti][q] = s9;
            }
        }
    }

    // ---- i-splats: 2 LDG.128 (AoS) + PRMT dups ----
    int w = tid >> 5, lane = tid & 31;
    int jbase = (w & 1) * 128;             // warp's j half (128 j's)
    int s0 = ti * TS + (w >> 1) * 64 + lane;
    int s1 = s0 + 32;

    uint4 ia = *reinterpret_cast<const uint4*>(&g_ia[b][s0][0]);
    uint4 ib = *reinterpret_cast<const uint4*>(&g_ia[b][s1][0]);

    __nv_bfloat162 X00 = u2b(__byte_perm(ia.x, ia.x, 0x1010));
    __nv_bfloat162 X01 = u2b(__byte_perm(ia.x, ia.x, 0x3232));
    __nv_bfloat162 X02 = u2b(__byte_perm(ia.y, ia.y, 0x1010));
    __nv_bfloat162 PX0 = u2b(__byte_perm(ia.y, ia.y, 0x3232));
    __nv_bfloat162 Y00 = u2b(__byte_perm(ia.z, ia.z, 0x1010));
    __nv_bfloat162 Y01 = u2b(__byte_perm(ia.z, ia.z, 0x3232));
    __nv_bfloat162 Y02 = u2b(__byte_perm(ia.w, ia.w, 0x1010));
    __nv_bfloat162 PY0 = u2b(__byte_perm(ia.w, ia.w, 0x3232));
    __nv_bfloat162 X10 = u2b(__byte_perm(ib.x, ib.x, 0x1010));
    __nv_bfloat162 X11 = u2b(__byte_perm(ib.x, ib.x, 0x3232));
    __nv_bfloat162 X12 = u2b(__byte_perm(ib.y, ib.y, 0x1010));
    __nv_bfloat162 PX1 = u2b(__byte_perm(ib.y, ib.y, 0x3232));
    __nv_bfloat162 Y10 = u2b(__byte_perm(ib.z, ib.z, 0x1010));
    __nv_bfloat162 Y11 = u2b(__byte_perm(ib.z, ib.z, 0x3232));
    __nv_bfloat162 Y12 = u2b(__byte_perm(ib.w, ib.w, 0x1010));
    __nv_bfloat162 PY1 = u2b(__byte_perm(ib.w, ib.w, 0x3232));

    __syncthreads();   // sjh ready

    float a00 = 0.f, a01 = 0.f, a10 = 0.f, a11 = 0.f;

    #define GROUP(CW0, CW1, CW2, CWN, DW0, DW1, DW2, DWN, XX0, XX1, XX2, PPX, YY0, YY1, YY2, PPY, S0, S1) { \
        __nv_bfloat162 tx_ = __hfma2(u2b(CW0), XX0, __hfma2(u2b(CW1), XX1,      \
                              __hfma2(u2b(CW2), XX2, __hadd2(u2b(CWN), PPX)))); \
        __nv_bfloat162 ty_ = __hfma2(u2b(DW0), YY0, __hfma2(u2b(DW1), YY1,      \
                              __hfma2(u2b(DW2), YY2, __hadd2(u2b(DWN), PPY)))); \
        unsigned pv_ = b2u(__hmul2(tx_, ty_));                                  \
        S0 += sqrt_abs(__uint_as_float(pv_ << 16));                             \
        S1 += sqrt_abs(__uint_as_float(pv_ & 0xffff0000u));                     \
    }

    #pragma unroll 2
    for (int jc = 0; jc < 16; jc++) {      // 8 j's per iteration, 128 total
        int jo = jbase + jc * 8;           // warp-uniform -> LDS broadcast
        uint4 c0 = *reinterpret_cast<const uint4*>(&sjh[0][jo]);
        uint4 c1 = *reinterpret_cast<const uint4*>(&sjh[1][jo]);
        uint4 c2 = *reinterpret_cast<const uint4*>(&sjh[2][jo]);
        uint4 cn = *reinterpret_cast<const uint4*>(&sjh[3][jo]);
        uint4 d0 = *reinterpret_cast<const uint4*>(&sjh[4][jo]);
        uint4 d1 = *reinterpret_cast<const uint4*>(&sjh[5][jo]);
        uint4 d2 = *reinterpret_cast<const uint4*>(&sjh[6][jo]);
        uint4 dn = *reinterpret_cast<const uint4*>(&sjh[7][jo]);

        GROUP(c0.x, c1.x, c2.x, cn.x, d0.x, d1.x, d2.x, dn.x,
              X00, X01, X02, PX0, Y00, Y01, Y02, PY0, a00, a01)
        GROUP(c0.x, c1.x, c2.x, cn.x, d0.x, d1.x, d2.x, dn.x,
              X10, X11, X12, PX1, Y10, Y11, Y12, PY1, a10, a11)
        GROUP(c0.y, c1.y, c2.y, cn.y, d0.y, d1.y, d2.y, dn.y,
              X00, X01, X02, PX0, Y00, Y01, Y02, PY0, a00, a01)
        GROUP(c0.y, c1.y, c2.y, cn.y, d0.y, d1.y, d2.y, dn.y,
              X10, X11, X12, PX1, Y10, Y11, Y12, PY1, a10, a11)
        GROUP(c0.z, c1.z, c2.z, cn.z, d0.z, d1.z, d2.z, dn.z,
              X00, X01, X02, PX0, Y00, Y01, Y02, PY0, a00, a01)
        GROUP(c0.z, c1.z, c2.z, cn.z, d0.z, d1.z, d2.z, dn.z,
              X10, X11, X12, PX1, Y10, Y11, Y12, PY1, a10, a11)
        GROUP(c0.w, c1.w, c2.w, cn.w, d0.w, d1.w, d2.w, dn.w,
              X00, X01, X02, PX0, Y00, Y01, Y02, PY0, a00, a01)
        GROUP(c0.w, c1.w, c2.w, cn.w, d0.w, d1.w, d2.w, dn.w,
              X10, X11, X12, PX1, Y10, Y11, Y12, PY1, a10, a11)
    }
    #undef GROUP

    float val = (a00 + a01) + (a10 + a11);

    // deterministic block reduce (8 warps)
    #pragma unroll
    for (int off = 16; off > 0; off >>= 1)
        val += __shfl_down_sync(0xffffffffu, val, off);
    __shared__ float wsum[TPB / 32];
    if ((tid & 31) == 0) wsum[tid >> 5] = val;
    __syncthreads();
    if (tid == 0) {
        float s = 0.f;
        #pragma unroll
        for (int ww = 0; ww < TPB / 32; ww++) s += wsum[ww];
        g_part[bid] = diag ? s : 2.0f * s;
    }

    // ---- last-block final reduction ----
    __shared__ bool isLast;
    if (tid == 0) {
        __threadfence();
        unsigned v = atomicAdd(&g_count, 1u);
        isLast = (v == (unsigned)(gridDim.x - 1));
    }
    __syncthreads();
    if (!isLast) return;
    __threadfence();

    int b2 = tid >> 5;                  // 0..7 (batch per warp)
    int l  = tid & 31;

    float wacc = 0.f;
    for (int k = l; k < TPAIRS; k += 32)
        wacc += g_part[b2 * TPAIRS + k];
    float a[9];
    #pragma unroll
    for (int q = 0; q < 9; q++)
        a[q] = (l < NT) ? g_aux[b2][l][q] : 0.f;

    #pragma unroll
    for (int off = 16; off > 0; off >>= 1) {
        wacc += __shfl_down_sync(0xffffffffu, wacc, off);
        #pragma unroll
        for (int q = 0; q < 9; q++)
            a[q] += __shfl_down_sync(0xffffffffu, a[q], off);
    }

    __shared__ float norms[BATCH];
    if (l == 0) {
        float n = (float)NPTS;
        float T = 2.0f * (n * a[0] - (a[1] * a[1] + a[2] * a[2] + a[3] * a[3]))
                + 2.0f * (n * a[4] - (a[5] * a[5] + a[6] * a[6] + a[7] * a[7]));
        float W = wacc - 2.0f * a[8];
        float S = T - 2.0f * W;
        if (S < 0.f) S = 0.f;
        norms[b2] = sqrtf(S);
    }
    __syncthreads();
    if (tid == 0) {
        float tot = 0.f;
        #pragma unroll
        for (int i = 0; i < BATCH; i++) tot += norms[i];
        float n = (float)NPTS;
        out[0] = tot / sqrtf(n * n - n) / (float)BATCH;
        g_count = 0;
    }
}

extern "C" void kernel_launch(void* const* d_in, const int* in_sizes, int n_in,
                              void* d_out, int out_size) {
    const float* x = (const float*)d_in[0];
    const float* y = (const float*)d_in[1];
    (void)in_sizes; (void)n_in; (void)out_size;
    prep_kernel<<<32, PREP_T>>>(x, y);
    drmsd_kernel<<<NBLK, TPB>>>(x, y, (float*)d_out);
}